// round 4
// baseline (speedup 1.0000x reference)
#include <cuda_runtime.h>
#include <cstdint>
#include <math.h>

#define V_SZ 100000
#define H_SZ 300
#define HP   304          // padded K (pads are zero-weighted, zero-filled)
#define B_SZ 64
#define L_SZ 64
#define NBLK_LOG 391      // 391*256 = 100096 >= V_SZ

typedef unsigned long long ull;

// ---------------- device scratch (no allocations allowed) ----------------
__device__ __align__(16) float g_h[2][HP * B_SZ];           // hidden, [k][b]
__device__ __align__(16) float g_xT[HP * B_SZ];             // decoder input
__device__ __align__(16) float g_xT_all[L_SZ * HP * B_SZ];  // encoder embeds
__device__ ull g_part[NBLK_LOG * B_SZ];

// ---------------- helpers ----------------
static __device__ __forceinline__ ull pk2(float lo, float hi) {
    ull r; asm("mov.b64 %0, {%1, %2};" : "=l"(r) : "f"(lo), "f"(hi)); return r;
}
static __device__ __forceinline__ void ffma2(ull& d, ull a, ull b) {
    asm("fma.rn.f32x2 %0, %1, %2, %0;" : "+l"(d) : "l"(a), "l"(b));
}
static __device__ __forceinline__ float2 upk2(ull v) {
    float2 r; asm("mov.b64 {%0, %1}, %2;" : "=f"(r.x), "=f"(r.y) : "l"(v)); return r;
}
static __device__ __forceinline__ unsigned ordf(float f) {
    unsigned u = __float_as_uint(f);
    return (u & 0x80000000u) ? ~u : (u | 0x80000000u);
}
static __device__ __forceinline__ ull umax64(ull a, ull b) { return a > b ? a : b; }

// cheap double exp: Cody-Waite + deg-9 Taylor, rel err ~7e-12. |x| <= ~90.
static __device__ __forceinline__ double dexp_(double x) {
    const double L2E   = 1.4426950408889634074;
    const double LN2HI = 6.93147180369123816490e-01;
    const double LN2LO = 1.90821492927058770002e-10;
    double t = x * L2E;
    int n = __double2int_rn(t);
    double nd = (double)n;
    double r = fma(-nd, LN2HI, x);
    r = fma(-nd, LN2LO, r);
    double p = 2.7557319223985893e-6;
    p = fma(p, r, 2.4801587301587302e-5);
    p = fma(p, r, 1.9841269841269841e-4);
    p = fma(p, r, 1.3888888888888889e-3);
    p = fma(p, r, 8.3333333333333333e-3);
    p = fma(p, r, 4.1666666666666667e-2);
    p = fma(p, r, 1.6666666666666667e-1);
    p = fma(p, r, 0.5);
    p = fma(p, r, 1.0);
    p = fma(p, r, 1.0);
    ull sb = (ull)(1023 + n) << 52;
    return p * __longlong_as_double((long long)sb);
}
// sigmoid/tanh: double path, abs err ~1e-12 (inputs clamped to +-30: beyond
// saturation at fp32 resolution)
static __device__ __forceinline__ float sigd(float x) {
    double xd = (double)fminf(fmaxf(x, -30.0f), 30.0f);
    double e = dexp_(-xd);
    double den = 1.0 + e;
    double r0 = (double)(1.0f / (float)den);       // seed ~2^-22
    r0 = r0 * fma(-den, r0, 2.0);                  // 1 NR -> ~2^-44
    return (float)r0;
}
static __device__ __forceinline__ float tanhd(float x) {
    double xd = (double)fminf(fmaxf(x, -30.0f), 30.0f);
    double e = dexp_(-2.0 * xd);
    double den = 1.0 + e;
    double r0 = (double)(1.0f / (float)den);
    r0 = r0 * fma(-den, r0, 2.0);
    return (float)fma(-2.0 * e, r0, 1.0);          // (1-e)/(1+e)
}

// ---------------- init: zero h (both buffers incl pads), x0 = relu(emb[0]) ----
__global__ void k_init(const float* __restrict__ emb) {
    int i = blockIdx.x * 256 + threadIdx.x;    // 76*256 = 19456 = HP*64 exact
    int k = i >> 6;
    g_h[0][i] = 0.0f;
    g_h[1][i] = 0.0f;
    g_xT[i] = (k < H_SZ) ? fmaxf(emb[k], 0.0f) : 0.0f;
}

// ---------------- gather encoder embeddings (+ zero pads) ----------------
__global__ void k_gather_enc(const int* __restrict__ input, const float* __restrict__ emb) {
    __shared__ int ids[B_SZ];
    int t = blockIdx.x, tid = threadIdx.x;
    if (tid < B_SZ) ids[tid] = input[t * B_SZ + tid];
    __syncthreads();
    for (int i = tid; i < B_SZ * H_SZ; i += 256) {
        int b = i / H_SZ, k = i - b * H_SZ;
        g_xT_all[((size_t)t * HP + k) * B_SZ + b] = emb[(size_t)ids[b] * H_SZ + k];
    }
    g_xT_all[((size_t)t * HP + H_SZ) * B_SZ + tid] = 0.0f;   // pads k=300..303
}

// ---------------- GRU step: grid 100 (3 n/block), block 256 --------------
__global__ __launch_bounds__(256) void k_gru(
    const float* __restrict__ W_ih, const float* __restrict__ W_hh,
    const float* __restrict__ b_ih, const float* __restrict__ b_hh,
    int xoff, int hin, int hout)
{
    __shared__ __align__(16) char smraw[36864];
    float (*Ws)[HP] = (float(*)[HP])smraw;    // [18][304] during main loop
    float* Red = (float*)smraw;               // [8][18][64] after (union)

    int tid = threadIdx.x;
    int n0 = blockIdx.x * 3;

    for (int i = tid; i < 18 * 75; i += 256) {
        int row = i / 75, q = i - row * 75;
        int rr = (row < 9) ? row : row - 9;
        int g = rr / 3, nl = rr - g * 3;
        const float* src = ((row < 9) ? W_ih : W_hh) + (size_t)(g * H_SZ + n0 + nl) * H_SZ;
        *(float4*)&Ws[row][q * 4] = *(const float4*)(src + q * 4);
    }
    if (tid < 18) { float4 z = {0.f, 0.f, 0.f, 0.f}; *(float4*)&Ws[tid][300] = z; }
    __syncthreads();

    const float* xp = (xoff >= 0) ? (g_xT_all + xoff) : g_xT;
    const float* hp = g_h[hin];
    int s = tid >> 4, bq = tid & 15;
    int ks = s * 19;

    ull a[18][2];
#pragma unroll
    for (int r = 0; r < 18; r++) { a[r][0] = 0ull; a[r][1] = 0ull; }

#pragma unroll 4
    for (int k = ks; k < ks + 19; k++) {
        ulonglong2 xq = *(const ulonglong2*)(xp + k * 64 + bq * 4);
        ulonglong2 hq = *(const ulonglong2*)(hp + k * 64 + bq * 4);
#pragma unroll
        for (int r = 0; r < 9; r++) {
            float wv = Ws[r][k];
            ull wd = pk2(wv, wv);
            ffma2(a[r][0], wd, xq.x);
            ffma2(a[r][1], wd, xq.y);
        }
#pragma unroll
        for (int r = 9; r < 18; r++) {
            float wv = Ws[r][k];
            ull wd = pk2(wv, wv);
            ffma2(a[r][0], wd, hq.x);
            ffma2(a[r][1], wd, hq.y);
        }
    }
    __syncthreads();   // done reading Ws (smem union with Red)

#pragma unroll
    for (int r = 0; r < 18; r++) {
        ull o0 = __shfl_xor_sync(0xffffffffu, a[r][0], 16);
        ull o1 = __shfl_xor_sync(0xffffffffu, a[r][1], 16);
        if ((tid & 16) == 0) {
            float2 p0 = upk2(a[r][0]), p1 = upk2(a[r][1]);
            float2 q0 = upk2(o0), q1 = upk2(o1);
            float4 v;
            v.x = p0.x + q0.x; v.y = p0.y + q0.y;
            v.z = p1.x + q1.x; v.w = p1.y + q1.y;
            *(float4*)&Red[(s >> 1) * 1152 + r * 64 + bq * 4] = v;
        }
    }
    __syncthreads();

    if (tid < 192) {
        int nl = tid >> 6, b = tid & 63;
        float sir = 0, siz = 0, sin_ = 0, shr = 0, shz = 0, shn = 0;
#pragma unroll
        for (int s2 = 0; s2 < 8; s2++) {
            const float* base = Red + s2 * 1152;
            sir  += base[nl * 64 + b];
            siz  += base[(3 + nl) * 64 + b];
            sin_ += base[(6 + nl) * 64 + b];
            shr  += base[(9 + nl) * 64 + b];
            shz  += base[(12 + nl) * 64 + b];
            shn  += base[(15 + nl) * 64 + b];
        }
        int n = n0 + nl;
        float r = sigd(sir + b_ih[n] + shr + b_hh[n]);
        float z = sigd(siz + b_ih[H_SZ + n] + shz + b_hh[H_SZ + n]);
        float nn = tanhd(sin_ + b_ih[2 * H_SZ + n] + r * (shn + b_hh[2 * H_SZ + n]));
        float hold = hp[n * 64 + b];
        g_h[hout][n * 64 + b] = (1.0f - z) * nn + z * hold;
    }
}

// ---------------- logits GEMM + fused per-block argmax -------------------
// grid 391, block 256. Thread: vy = tid>>3 (8 vocab rows at vbase+iv),
// bx = tid&7 (8 batches). No smem in main loop: W via LDG.128 (warp-broadcast
// over bx lanes, L1-served), h via LDG.128 (1KB sliding window in L1).
__global__ __launch_bounds__(256) void k_logits(
    int hin, const float* __restrict__ W, const float* __restrict__ bias)
{
    __shared__ ull red[2048];     // [32 vy][64 b]

    int tid = threadIdx.x, blk = blockIdx.x;
    int v0 = blk * 256;
    int vy = tid >> 3, bx = tid & 7;
    int vr = v0 + vy * 8;
    int vbase = (vr > V_SZ - 8) ? (V_SZ - 8) : vr;   // clamp only when all-invalid
    const float* Wp = W + (size_t)vbase * H_SZ;
    const float* hT = g_h[hin];

    ull acc[8][4];
#pragma unroll
    for (int i = 0; i < 8; i++)
#pragma unroll
        for (int j = 0; j < 4; j++) acc[i][j] = 0ull;

#pragma unroll 3
    for (int k0 = 0; k0 < H_SZ; k0 += 4) {
        ulonglong2 hA0 = *(const ulonglong2*)(hT + (k0 + 0) * 64 + bx * 8);
        ulonglong2 hB0 = *(const ulonglong2*)(hT + (k0 + 0) * 64 + bx * 8 + 4);
        ulonglong2 hA1 = *(const ulonglong2*)(hT + (k0 + 1) * 64 + bx * 8);
        ulonglong2 hB1 = *(const ulonglong2*)(hT + (k0 + 1) * 64 + bx * 8 + 4);
        ulonglong2 hA2 = *(const ulonglong2*)(hT + (k0 + 2) * 64 + bx * 8);
        ulonglong2 hB2 = *(const ulonglong2*)(hT + (k0 + 2) * 64 + bx * 8 + 4);
        ulonglong2 hA3 = *(const ulonglong2*)(hT + (k0 + 3) * 64 + bx * 8);
        ulonglong2 hB3 = *(const ulonglong2*)(hT + (k0 + 3) * 64 + bx * 8 + 4);
#pragma unroll
        for (int iv = 0; iv < 8; iv++) {
            float4 wv = *(const float4*)(Wp + iv * H_SZ + k0);
            ull w;
            w = pk2(wv.x, wv.x);
            ffma2(acc[iv][0], w, hA0.x); ffma2(acc[iv][1], w, hA0.y);
            ffma2(acc[iv][2], w, hB0.x); ffma2(acc[iv][3], w, hB0.y);
            w = pk2(wv.y, wv.y);
            ffma2(acc[iv][0], w, hA1.x); ffma2(acc[iv][1], w, hA1.y);
            ffma2(acc[iv][2], w, hB1.x); ffma2(acc[iv][3], w, hB1.y);
            w = pk2(wv.z, wv.z);
            ffma2(acc[iv][0], w, hA2.x); ffma2(acc[iv][1], w, hA2.y);
            ffma2(acc[iv][2], w, hB2.x); ffma2(acc[iv][3], w, hB2.y);
            w = pk2(wv.w, wv.w);
            ffma2(acc[iv][0], w, hA3.x); ffma2(acc[iv][1], w, hA3.y);
            ffma2(acc[iv][2], w, hB3.x); ffma2(acc[iv][3], w, hB3.y);
        }
    }

    // fused argmax: key = (ordered_float << 32) | ~v  (JAX first-index ties)
    ull lm[8];
#pragma unroll
    for (int j = 0; j < 8; j++) lm[j] = 0ull;
#pragma unroll
    for (int iv = 0; iv < 8; iv++) {
        int v = vr + iv;
        if (v < V_SZ) {
            float bj = bias[v];
            ull tg = (ull)(~(unsigned)v);
            float2 p0 = upk2(acc[iv][0]), p1 = upk2(acc[iv][1]);
            float2 p2 = upk2(acc[iv][2]), p3 = upk2(acc[iv][3]);
            lm[0] = umax64(lm[0], ((ull)ordf(p0.x + bj) << 32) | tg);
            lm[1] = umax64(lm[1], ((ull)ordf(p0.y + bj) << 32) | tg);
            lm[2] = umax64(lm[2], ((ull)ordf(p1.x + bj) << 32) | tg);
            lm[3] = umax64(lm[3], ((ull)ordf(p1.y + bj) << 32) | tg);
            lm[4] = umax64(lm[4], ((ull)ordf(p2.x + bj) << 32) | tg);
            lm[5] = umax64(lm[5], ((ull)ordf(p2.y + bj) << 32) | tg);
            lm[6] = umax64(lm[6], ((ull)ordf(p3.x + bj) << 32) | tg);
            lm[7] = umax64(lm[7], ((ull)ordf(p3.y + bj) << 32) | tg);
        }
    }
#pragma unroll
    for (int j = 0; j < 8; j++) red[vy * 64 + bx * 8 + j] = lm[j];
    __syncthreads();
    if (tid < B_SZ) {
        ull m = red[tid];
#pragma unroll
        for (int r = 1; r < 32; r++) m = umax64(m, red[r * 64 + tid]);
        g_part[blk * B_SZ + tid] = m;
    }
}

// ---------------- finalize: global argmax per batch, emit id, next x -----
__global__ void k_finalize(const float* __restrict__ emb, float* __restrict__ out, int t) {
    __shared__ ull sred[256];
    __shared__ int sid;
    int b = blockIdx.x, tid = threadIdx.x;
    ull m = 0;
    for (int i = tid; i < NBLK_LOG; i += 256) m = umax64(m, g_part[i * B_SZ + b]);
    sred[tid] = m;
    __syncthreads();
    for (int s = 128; s > 0; s >>= 1) {
        if (tid < s) sred[tid] = umax64(sred[tid], sred[tid + s]);
        __syncthreads();
    }
    if (tid == 0) {
        unsigned id = ~(unsigned)(sred[0] & 0xffffffffull);
        sid = (int)id;
        out[t * B_SZ + b] = (float)id;
    }
    __syncthreads();
    int id = sid;
    for (int k = tid; k < H_SZ; k += 256)
        g_xT[k * 64 + b] = fmaxf(emb[(size_t)id * H_SZ + k], 0.0f);
}

// ---------------- launch ----------------
extern "C" void kernel_launch(void* const* d_in, const int* in_sizes, int n_in,
                              void* d_out, int out_size) {
    const int*   input = (const int*)d_in[0];
    const float* emb   = (const float*)d_in[1];
    const float* eWih  = (const float*)d_in[2];
    const float* eWhh  = (const float*)d_in[3];
    const float* ebih  = (const float*)d_in[4];
    const float* ebhh  = (const float*)d_in[5];
    const float* dWih  = (const float*)d_in[6];
    const float* dWhh  = (const float*)d_in[7];
    const float* dbih  = (const float*)d_in[8];
    const float* dbhh  = (const float*)d_in[9];
    const float* oW    = (const float*)d_in[10];
    const float* ob    = (const float*)d_in[11];
    float* out = (float*)d_out;

    k_init<<<76, 256>>>(emb);
    k_gather_enc<<<L_SZ, 256>>>(input, emb);

    for (int t = 0; t < L_SZ; t++)
        k_gru<<<100, 256>>>(eWih, eWhh, ebih, ebhh, t * HP * B_SZ, t & 1, (t + 1) & 1);

    int p = 0;
    for (int t = 0; t < L_SZ; t++) {
        k_gru<<<100, 256>>>(dWih, dWhh, dbih, dbhh, -1, p, 1 - p);
        k_logits<<<NBLK_LOG, 256>>>(1 - p, oW, ob);
        k_finalize<<<B_SZ, 256>>>(emb, out, t);
        p = 1 - p;
    }
}

// round 5
// speedup vs baseline: 1.7076x; 1.7076x over previous
#include <cuda_runtime.h>
#include <cstdint>
#include <math.h>

#define V_SZ 100000
#define H_SZ 300
#define HP   304          // padded K (pads zero-weighted + zero-filled)
#define B_SZ 64
#define L_SZ 64
#define NBLK_LOG 391      // 391*256 = 100096 >= V_SZ

typedef unsigned long long ull;

// ---------------- device scratch ----------------
__device__ __align__(16) float g_h[2][HP * B_SZ];           // hidden, [k][b]
__device__ __align__(16) float g_xT[HP * B_SZ];             // decoder input
__device__ __align__(16) float g_xT_all[L_SZ * HP * B_SZ];  // encoder embeds
__device__ ull g_part[NBLK_LOG * B_SZ];

// ---------------- helpers ----------------
static __device__ __forceinline__ ull pk2(float lo, float hi) {
    ull r; asm("mov.b64 %0, {%1, %2};" : "=l"(r) : "f"(lo), "f"(hi)); return r;
}
static __device__ __forceinline__ void ffma2(ull& d, ull a, ull b) {
    asm("fma.rn.f32x2 %0, %1, %2, %0;" : "+l"(d) : "l"(a), "l"(b));
}
static __device__ __forceinline__ float2 upk2(ull v) {
    float2 r; asm("mov.b64 {%0, %1}, %2;" : "=f"(r.x), "=f"(r.y) : "l"(v)); return r;
}
static __device__ __forceinline__ unsigned ordf(float f) {
    unsigned u = __float_as_uint(f);
    return (u & 0x80000000u) ? ~u : (u | 0x80000000u);
}
static __device__ __forceinline__ ull umax64(ull a, ull b) { return a > b ? a : b; }
static __device__ __forceinline__ unsigned s2u(const void* p) {
    return (unsigned)__cvta_generic_to_shared(p);
}
#define CP16(dst, src) asm volatile("cp.async.cg.shared.global [%0], [%1], 16;" :: "r"(dst), "l"(src))

// cheap double exp (Cody-Waite + deg-9), rel err ~7e-12
static __device__ __forceinline__ double dexp_(double x) {
    const double L2E   = 1.4426950408889634074;
    const double LN2HI = 6.93147180369123816490e-01;
    const double LN2LO = 1.90821492927058770002e-10;
    int n = __double2int_rn(x * L2E);
    double nd = (double)n;
    double r = fma(-nd, LN2HI, x);
    r = fma(-nd, LN2LO, r);
    double p = 2.7557319223985893e-6;
    p = fma(p, r, 2.4801587301587302e-5);
    p = fma(p, r, 1.9841269841269841e-4);
    p = fma(p, r, 1.3888888888888889e-3);
    p = fma(p, r, 8.3333333333333333e-3);
    p = fma(p, r, 4.1666666666666667e-2);
    p = fma(p, r, 1.6666666666666667e-1);
    p = fma(p, r, 0.5);
    p = fma(p, r, 1.0);
    p = fma(p, r, 1.0);
    return p * __longlong_as_double((long long)((ull)(1023 + n) << 52));
}
static __device__ __forceinline__ float sigd(float x) {
    double xd = (double)fminf(fmaxf(x, -30.0f), 30.0f);
    double e = dexp_(-xd);
    double den = 1.0 + e;
    double r0 = (double)(1.0f / (float)den);
    r0 = r0 * fma(-den, r0, 2.0);
    return (float)r0;
}
static __device__ __forceinline__ float tanhd(float x) {
    double xd = (double)fminf(fmaxf(x, -30.0f), 30.0f);
    double e = dexp_(-2.0 * xd);
    double den = 1.0 + e;
    double r0 = (double)(1.0f / (float)den);
    r0 = r0 * fma(-den, r0, 2.0);
    return (float)fma(-2.0 * e, r0, 1.0);
}

// ---------------- init ----------------
__global__ void k_init(const float* __restrict__ emb) {
    int i = blockIdx.x * 256 + threadIdx.x;    // 76*256 = HP*64 exact
    int k = i >> 6;
    g_h[0][i] = 0.0f;
    g_h[1][i] = 0.0f;
    g_xT[i] = (k < H_SZ) ? fmaxf(emb[k], 0.0f) : 0.0f;
}

// ---------------- gather encoder embeddings (+ zero pads) ----------------
__global__ void k_gather_enc(const int* __restrict__ input, const float* __restrict__ emb) {
    __shared__ int ids[B_SZ];
    int t = blockIdx.x, tid = threadIdx.x;
    if (tid < B_SZ) ids[tid] = input[t * B_SZ + tid];
    __syncthreads();
    for (int i = tid; i < B_SZ * H_SZ; i += 256) {
        int b = i / H_SZ, k = i - b * H_SZ;
        g_xT_all[((size_t)t * HP + k) * B_SZ + b] = emb[(size_t)ids[b] * H_SZ + k];
    }
    g_xT_all[((size_t)t * HP + H_SZ) * B_SZ + tid] = 0.0f;   // pads k=300..303
}

// ---------------- GRU step: grid 100 (3 n/block), block 512 --------------
// warp = K-slice (16 slices of 19), lane = batch-pair (1 ull covers 2 batches)
__global__ __launch_bounds__(512) void k_gru(
    const float* __restrict__ W_ih, const float* __restrict__ W_hh,
    const float* __restrict__ b_ih, const float* __restrict__ b_hh,
    int xoff, int hin, int hout)
{
    __shared__ __align__(16) char smraw[36864];
    float (*Ws)[HP] = (float(*)[HP])smraw;    // [18][304] during main loop
    ull* Red = (ull*)smraw;                   // [8][18][32] ull after (union)

    int tid = threadIdx.x;
    int n0 = blockIdx.x * 3;
    int w = tid >> 5, lane = tid & 31;

    // stage 18 weight rows (rows 0..8: W_ih gate g,row nl; 9..17: W_hh)
    for (int i = tid; i < 18 * 75; i += 512) {
        int row = i / 75, q = i - row * 75;
        int rr = (row < 9) ? row : row - 9;
        int g = rr / 3, nl = rr - g * 3;
        const float* src = ((row < 9) ? W_ih : W_hh) + (size_t)(g * H_SZ + n0 + nl) * H_SZ;
        *(float4*)&Ws[row][q * 4] = *(const float4*)(src + q * 4);
    }
    if (tid < 18) { float4 z = {0.f, 0.f, 0.f, 0.f}; *(float4*)&Ws[tid][300] = z; }
    __syncthreads();

    const float* xp = (xoff >= 0) ? (g_xT_all + xoff) : g_xT;
    const float* hp = g_h[hin];
    int ks = w * 19;

    ull a[18];
#pragma unroll
    for (int r = 0; r < 18; r++) a[r] = 0ull;

#pragma unroll 4
    for (int k = ks; k < ks + 19; k++) {
        ull xq = *(const ull*)(xp + k * 64 + lane * 2);
        ull hq = *(const ull*)(hp + k * 64 + lane * 2);
#pragma unroll
        for (int r = 0; r < 9; r++) ffma2(a[r], pk2(Ws[r][k], Ws[r][k]), xq);
#pragma unroll
        for (int r = 9; r < 18; r++) ffma2(a[r], pk2(Ws[r][k], Ws[r][k]), hq);
    }
    __syncthreads();   // done reading Ws (smem union with Red)

    // cross-warp reduce: warps 8..15 write, warps 0..7 add + write
    if (w >= 8) {
#pragma unroll
        for (int r = 0; r < 18; r++) Red[((w - 8) * 18 + r) * 32 + lane] = a[r];
    }
    __syncthreads();
    if (w < 8) {
#pragma unroll
        for (int r = 0; r < 18; r++) {
            ull o = Red[(w * 18 + r) * 32 + lane];
            float2 pa = upk2(a[r]), po = upk2(o);
            Red[(w * 18 + r) * 32 + lane] = pk2(pa.x + po.x, pa.y + po.y);
        }
    }
    __syncthreads();

    if (tid < 192) {
        int nl = tid >> 6, b = tid & 63;
        const float* Redf = (const float*)Red;   // [s2][r][64 floats b-ordered]
        float sir = 0, siz = 0, sin_ = 0, shr = 0, shz = 0, shn = 0;
#pragma unroll
        for (int s2 = 0; s2 < 8; s2++) {
            const float* base = Redf + s2 * 1152;
            sir  += base[nl * 64 + b];
            siz  += base[(3 + nl) * 64 + b];
            sin_ += base[(6 + nl) * 64 + b];
            shr  += base[(9 + nl) * 64 + b];
            shz  += base[(12 + nl) * 64 + b];
            shn  += base[(15 + nl) * 64 + b];
        }
        int n = n0 + nl;
        float r = sigd(sir + b_ih[n] + shr + b_hh[n]);
        float z = sigd(siz + b_ih[H_SZ + n] + shz + b_hh[H_SZ + n]);
        float nn = tanhd(sin_ + b_ih[2 * H_SZ + n] + r * (shn + b_hh[2 * H_SZ + n]));
        float hold = hp[n * 64 + b];
        g_h[hout][n * 64 + b] = (1.0f - z) * nn + z * hold;
    }
}

// ---------------- logits GEMM + fused per-block argmax -------------------
// grid 391, block 128: vy = tid>>3 (16 groups x 16 vocab rows), bx = tid&7
// (8 batches). Per-thread 16v x 8b tile -> 1.5 B/FFMA2 (crossbar < FMA).
#define KCH 20
__global__ __launch_bounds__(128) void k_logits(
    int hin, const float* __restrict__ W, const float* __restrict__ bias)
{
    __shared__ __align__(16) char sm[30208];
    float* Wt = (float*)sm;               // 256 rows x 24 floats + 16B skew per 8 rows
    float* hs = (float*)(sm + 25088);     // [20][64]
    ull*   red = (ull*)sm;                // [16][64] after compute (union)

    int tid = threadIdx.x, blk = blockIdx.x;
    int v0 = blk * 256;
    int vy = tid >> 3, bx = tid & 7;
    const float* hT = g_h[hin];

    ull acc[16][4];
#pragma unroll
    for (int i = 0; i < 16; i++)
#pragma unroll
        for (int j = 0; j < 4; j++) acc[i][j] = 0ull;

    for (int c = 0; c < H_SZ / KCH; c++) {    // 15 chunks
        int k0 = c * KCH;
        // stage W chunk: 1280 x 16B cp.async, skewed dst
        for (int i = tid; i < 1280; i += 128) {
            int vl = i / 5, q = i - vl * 5;
            int rv = v0 + vl; if (rv > V_SZ - 1) rv = V_SZ - 1;
            unsigned dst = s2u(Wt + vl * 24 + (vl >> 3) * 4 + q * 4);
            CP16(dst, W + (size_t)rv * H_SZ + k0 + q * 4);
        }
        // stage h chunk: 320 x 16B
        const float* hb = hT + k0 * 64;
        for (int i = tid; i < 320; i += 128) CP16(s2u(hs + i * 4), hb + i * 4);
        asm volatile("cp.async.commit_group;");
        asm volatile("cp.async.wait_group 0;");
        __syncthreads();

#pragma unroll
        for (int kk = 0; kk < KCH; kk += 4) {
            ulonglong2 hA0 = *(const ulonglong2*)(hs + (kk + 0) * 64 + bx * 8);
            ulonglong2 hA1 = *(const ulonglong2*)(hs + (kk + 1) * 64 + bx * 8);
            ulonglong2 hA2 = *(const ulonglong2*)(hs + (kk + 2) * 64 + bx * 8);
            ulonglong2 hA3 = *(const ulonglong2*)(hs + (kk + 3) * 64 + bx * 8);
#pragma unroll
            for (int iv = 0; iv < 16; iv++) {
                int vl = vy * 16 + iv;
                const float* wp = Wt + vl * 24 + (vl >> 3) * 4 + kk;
                float4 wv = *(const float4*)wp;
                ull w;
                w = pk2(wv.x, wv.x);
                ffma2(acc[iv][0], w, hA0.x); ffma2(acc[iv][1], w, hA0.y);
                w = pk2(wv.y, wv.y);
                ffma2(acc[iv][0], w, hA1.x); ffma2(acc[iv][1], w, hA1.y);
                w = pk2(wv.z, wv.z);
                ffma2(acc[iv][0], w, hA2.x); ffma2(acc[iv][1], w, hA2.y);
                w = pk2(wv.w, wv.w);
                ffma2(acc[iv][0], w, hA3.x); ffma2(acc[iv][1], w, hA3.y);
            }
#pragma unroll
            for (int kk2 = 0; kk2 < 4; kk2++) {
                // second half of the 8 batches
            }
            ulonglong2 hB0 = *(const ulonglong2*)(hs + (kk + 0) * 64 + bx * 8 + 4);
            ulonglong2 hB1 = *(const ulonglong2*)(hs + (kk + 1) * 64 + bx * 8 + 4);
            ulonglong2 hB2 = *(const ulonglong2*)(hs + (kk + 2) * 64 + bx * 8 + 4);
            ulonglong2 hB3 = *(const ulonglong2*)(hs + (kk + 3) * 64 + bx * 8 + 4);
#pragma unroll
            for (int iv = 0; iv < 16; iv++) {
                int vl = vy * 16 + iv;
                const float* wp = Wt + vl * 24 + (vl >> 3) * 4 + kk;
                float4 wv = *(const float4*)wp;
                ull w;
                w = pk2(wv.x, wv.x);
                ffma2(acc[iv][2], w, hB0.x); ffma2(acc[iv][3], w, hB0.y);
                w = pk2(wv.y, wv.y);
                ffma2(acc[iv][2], w, hB1.x); ffma2(acc[iv][3], w, hB1.y);
                w = pk2(wv.z, wv.z);
                ffma2(acc[iv][2], w, hB2.x); ffma2(acc[iv][3], w, hB2.y);
                w = pk2(wv.w, wv.w);
                ffma2(acc[iv][2], w, hB3.x); ffma2(acc[iv][3], w, hB3.y);
            }
        }
        __syncthreads();
    }

    // fused argmax: key = (ordered_float << 32) | ~v  (JAX first-index ties)
    ull lm[8];
#pragma unroll
    for (int j = 0; j < 8; j++) lm[j] = 0ull;
#pragma unroll
    for (int iv = 0; iv < 16; iv++) {
        int v = v0 + vy * 16 + iv;
        if (v < V_SZ) {
            float bj = bias[v];
            ull tg = (ull)(~(unsigned)v);
            float2 p0 = upk2(acc[iv][0]), p1 = upk2(acc[iv][1]);
            float2 p2 = upk2(acc[iv][2]), p3 = upk2(acc[iv][3]);
            lm[0] = umax64(lm[0], ((ull)ordf(p0.x + bj) << 32) | tg);
            lm[1] = umax64(lm[1], ((ull)ordf(p0.y + bj) << 32) | tg);
            lm[2] = umax64(lm[2], ((ull)ordf(p1.x + bj) << 32) | tg);
            lm[3] = umax64(lm[3], ((ull)ordf(p1.y + bj) << 32) | tg);
            lm[4] = umax64(lm[4], ((ull)ordf(p2.x + bj) << 32) | tg);
            lm[5] = umax64(lm[5], ((ull)ordf(p2.y + bj) << 32) | tg);
            lm[6] = umax64(lm[6], ((ull)ordf(p3.x + bj) << 32) | tg);
            lm[7] = umax64(lm[7], ((ull)ordf(p3.y + bj) << 32) | tg);
        }
    }
    __syncthreads();   // everyone done reading Wt/hs before red overwrites
#pragma unroll
    for (int j = 0; j < 8; j++) {
        int b = bx * 8 + ((j & 3) >> 1) * 0;   // mapping below
    }
    // lm[0..3] = batches bx*8+0..3, lm[4..7] = bx*8+4..7
#pragma unroll
    for (int j = 0; j < 8; j++) red[vy * 64 + bx * 8 + j] = lm[j];
    __syncthreads();
    if (tid < B_SZ) {
        ull m = red[tid];
#pragma unroll
        for (int r = 1; r < 16; r++) m = umax64(m, red[r * 64 + tid]);
        g_part[blk * B_SZ + tid] = m;
    }
}

// ---------------- finalize ----------------
__global__ void k_finalize(const float* __restrict__ emb, float* __restrict__ out, int t) {
    __shared__ ull sred[256];
    __shared__ int sid;
    int b = blockIdx.x, tid = threadIdx.x;
    ull m = 0;
    for (int i = tid; i < NBLK_LOG; i += 256) m = umax64(m, g_part[i * B_SZ + b]);
    sred[tid] = m;
    __syncthreads();
    for (int s = 128; s > 0; s >>= 1) {
        if (tid < s) sred[tid] = umax64(sred[tid], sred[tid + s]);
        __syncthreads();
    }
    if (tid == 0) {
        unsigned id = ~(unsigned)(sred[0] & 0xffffffffull);
        sid = (int)id;
        out[t * B_SZ + b] = (float)id;
    }
    __syncthreads();
    int id = sid;
    for (int k = tid; k < H_SZ; k += 256)
        g_xT[k * 64 + b] = fmaxf(emb[(size_t)id * H_SZ + k], 0.0f);
}

// ---------------- launch ----------------
extern "C" void kernel_launch(void* const* d_in, const int* in_sizes, int n_in,
                              void* d_out, int out_size) {
    const int*   input = (const int*)d_in[0];
    const float* emb   = (const float*)d_in[1];
    const float* eWih  = (const float*)d_in[2];
    const float* eWhh  = (const float*)d_in[3];
    const float* ebih  = (const float*)d_in[4];
    const float* ebhh  = (const float*)d_in[5];
    const float* dWih  = (const float*)d_in[6];
    const float* dWhh  = (const float*)d_in[7];
    const float* dbih  = (const float*)d_in[8];
    const float* dbhh  = (const float*)d_in[9];
    const float* oW    = (const float*)d_in[10];
    const float* ob    = (const float*)d_in[11];
    float* out = (float*)d_out;

    k_init<<<76, 256>>>(emb);
    k_gather_enc<<<L_SZ, 256>>>(input, emb);

    for (int t = 0; t < L_SZ; t++)
        k_gru<<<100, 512>>>(eWih, eWhh, ebih, ebhh, t * HP * B_SZ, t & 1, (t + 1) & 1);

    int p = 0;
    for (int t = 0; t < L_SZ; t++) {
        k_gru<<<100, 512>>>(dWih, dWhh, dbih, dbhh, -1, p, 1 - p);
        k_logits<<<NBLK_LOG, 128>>>(1 - p, oW, ob);
        k_finalize<<<B_SZ, 256>>>(emb, out, t);
        p = 1 - p;
    }
}